// round 16
// baseline (speedup 1.0000x reference)
#include <cuda_runtime.h>
#include <cstdint>
#include <math.h>

#define NN 50000
#define DD 200
#define RR 480
#define TT 4
#define EE 100000
#define SLOPE 0.22916666666666666f

// ---------------- device scratch (no allocations) ----------------
__device__ float g_h[NN * DD];       // initial h only (t=0); later h lives in out[t-1]
__device__ float g_hhA[NN * DD];
__device__ float g_agg[NN * DD];
__device__ float g_gacc[NN * DD];    // raw time-gate GEMM acc
__device__ float g_h0[RR * DD];
__device__ float g_Bt[5 * DD * DD + 4096];
__device__ float g_gic[RR * 600];
__device__ float g_gi[RR * 600];
__device__ float g_gh[RR * 600];
__device__ float g_xmean[RR * DD];
__device__ int g_iblk[2 * RR + NN];  // rcnt | rwc | deg
__device__ int g_roff[RR + 1];
__device__ int g_rlist[2 * EE];

// ---------------- helpers ----------------
__device__ __forceinline__ uint32_t smem_u32(const void* p) {
    uint32_t a;
    asm("{ .reg .u64 t; cvta.to.shared.u64 t, %1; cvt.u32.u64 %0, t; }" : "=r"(a) : "l"(p));
    return a;
}

#define CP16(sm_addr, gptr) \
    asm volatile("cp.async.ca.shared.global [%0], [%1], 16;" :: "r"(sm_addr), "l"(gptr))
#define CP16Z(sm_addr, gptr, sz) \
    asm volatile("cp.async.ca.shared.global [%0], [%1], 16, %2;" \
                 :: "r"(sm_addr), "l"(gptr), "r"(sz))
#define CP_COMMIT() asm volatile("cp.async.commit_group;" ::: "memory")
#define CP_WAIT2()  asm volatile("cp.async.wait_group 2;" ::: "memory")

#define MMA_TF32(d, a, b0, b1)                                                    \
    asm volatile("mma.sync.aligned.m16n8k8.row.col.f32.tf32.tf32.f32 "            \
                 "{%0,%1,%2,%3}, {%4,%5,%6,%7}, {%8,%9}, {%0,%1,%2,%3};"          \
                 : "+f"((d)[0]), "+f"((d)[1]), "+f"((d)[2]), "+f"((d)[3])         \
                 : "r"((a)[0]), "r"((a)[1]), "r"((a)[2]), "r"((a)[3]),            \
                   "r"(b0), "r"(b1))

__device__ __forceinline__ void red_add_v4(float* p, float4 v) {
    asm volatile("red.global.add.v4.f32 [%0], {%1, %2, %3, %4};"
                 :: "l"(p), "f"(v.x), "f"(v.y), "f"(v.z), "f"(v.w) : "memory");
}

// ---------------- fused tensor-core GEMM (tf32, BK=16, 3-stage pipe) ------------
// by==0: acc = sum_parts Apart @ Bpart^T; after part0 acc *= 1/max(deg,1).
//   if tgout==null: out = rrelu(acc); optional zero zagg rows.
//   if tgout!=null: fused layer-1 + time gate:
//       o = rrelu(acc); ssq_row = sum(o^2) (CTA-local);
//       tw = sigmoid(gacc + tgbt[col]); hn = tw*(o*rsqrt(ssq)) + (1-tw)*hold;
//       tgout = hn; optional zero zagg rows.
// by==1 (tgB != null): acc = A1 @ tgB^T (1 part); gaccp = acc (raw).
#define STG 6720
#define BOFF 2560

__global__ void __launch_bounds__(256, 2)
k_mma_gemm(const float* __restrict__ A0in, const float* __restrict__ A1,
           const float* __restrict__ B0in, const float* __restrict__ B1g,
           const int* __restrict__ degv, float* __restrict__ outp,
           float* __restrict__ zaggp,
           const float* __restrict__ tgB, float* __restrict__ gaccp,
           const float* __restrict__ tgbt, const float* __restrict__ tghold,
           float* __restrict__ tgout, int nparts) {
    __shared__ __align__(16) float sm[3 * STG];
    __shared__ float s_ssq[128];
    int tid = threadIdx.x, lane = tid & 31, wid = tid >> 5;
    int wr = wid >> 1, wc = wid & 1;
    int row0 = blockIdx.x * 128;
    bool tg = (blockIdx.y == 1);
    const float* A0 = tg ? A1 : A0in;
    const float* B0g = tg ? tgB : B0in;
    int np = tg ? 1 : nparts;
    if (tg) zaggp = nullptr;
    if (tid < 128) s_ssq[tid] = 0.f;

    float acc[2][13][4];
    #pragma unroll
    for (int mt = 0; mt < 2; ++mt)
        #pragma unroll
        for (int nt = 0; nt < 13; ++nt)
            #pragma unroll
            for (int q = 0; q < 4; ++q) acc[mt][nt][q] = 0.f;

    const int nk = np * 13;

    auto issue = [&](int c) {
        if (c < nk) {
            const float* A = (c < 13) ? A0 : A1;
            const float* B = (c < 13) ? B0g : B1g;
            int k0 = ((c < 13) ? c : c - 13) * 16;
            int base = (c % 3) * STG;
            #pragma unroll
            for (int i = 0; i < 2; ++i) {
                int idx = tid + i * 256;
                int r = idx >> 2, c4 = idx & 3;
                int row = row0 + r;
                if (row >= NN) row = NN - 1;
                int kk = k0 + c4 * 4;
                uint32_t sz = (kk < DD) ? 16u : 0u;
                CP16Z(smem_u32(&sm[base + r * 20 + c4 * 4]),
                      A + (size_t)row * DD + (kk < DD ? kk : 0), sz);
            }
            #pragma unroll
            for (int i = 0; i < 4; ++i) {
                int idx = tid + i * 256;
                if (idx < 832) {
                    int n = idx >> 2, c4 = idx & 3;
                    int kk = k0 + c4 * 4;
                    uint32_t sz = (kk < DD) ? 16u : 0u;
                    CP16Z(smem_u32(&sm[base + BOFF + n * 20 + c4 * 4]),
                          B + (size_t)n * DD + (kk < DD ? kk : 0), sz);
                }
            }
        }
        CP_COMMIT();
    };

    issue(0); issue(1); issue(2);
    for (int c = 0; c < nk; ++c) {
        CP_WAIT2();
        __syncthreads();
        int base = (c % 3) * STG;
        int rb = wr * 32 + (lane >> 2);
        int kk = lane & 3;
        int nb = wc * 104 + (lane >> 2);
        #pragma unroll
        for (int ks = 0; ks < 2; ++ks) {
            int ko = ks * 8;
            uint32_t a[2][4];
            #pragma unroll
            for (int mt = 0; mt < 2; ++mt) {
                int r = rb + mt * 16;
                a[mt][0] = __float_as_uint(sm[base + r * 20 + ko + kk]);
                a[mt][1] = __float_as_uint(sm[base + (r + 8) * 20 + ko + kk]);
                a[mt][2] = __float_as_uint(sm[base + r * 20 + ko + kk + 4]);
                a[mt][3] = __float_as_uint(sm[base + (r + 8) * 20 + ko + kk + 4]);
            }
            #pragma unroll
            for (int nt = 0; nt < 13; ++nt) {
                int n = nb + nt * 8;
                uint32_t b0 = __float_as_uint(sm[base + BOFF + n * 20 + ko + kk]);
                uint32_t b1 = __float_as_uint(sm[base + BOFF + n * 20 + ko + kk + 4]);
                MMA_TF32(acc[0][nt], a[0], b0, b1);
                MMA_TF32(acc[1][nt], a[1], b0, b1);
            }
        }
        if (c == 12 && np == 2) {
            #pragma unroll
            for (int mt = 0; mt < 2; ++mt) {
                int r = row0 + wr * 32 + mt * 16 + (lane >> 2);
                int r2 = r + 8;
                float n0 = 1.f / fmaxf((float)degv[r < NN ? r : NN - 1], 1.f);
                float n1 = 1.f / fmaxf((float)degv[r2 < NN ? r2 : NN - 1], 1.f);
                #pragma unroll
                for (int nt = 0; nt < 13; ++nt) {
                    acc[mt][nt][0] *= n0; acc[mt][nt][1] *= n0;
                    acc[mt][nt][2] *= n1; acc[mt][nt][3] *= n1;
                }
            }
        }
        __syncthreads();
        issue(c + 3);
    }

    // ---- epilogue ----
    if (tg) {
        // raw acc -> gacc
        #pragma unroll
        for (int mt = 0; mt < 2; ++mt) {
            int r = row0 + wr * 32 + mt * 16 + (lane >> 2);
            #pragma unroll
            for (int nt = 0; nt < 13; ++nt) {
                int col = wc * 104 + nt * 8 + (lane & 3) * 2;
                if (col >= DD) continue;
                #pragma unroll
                for (int half = 0; half < 2; ++half) {
                    int row = r + half * 8;
                    if (row >= NN) continue;
                    float2 o;
                    o.x = acc[mt][nt][half * 2];
                    o.y = acc[mt][nt][half * 2 + 1];
                    *(float2*)&gaccp[(size_t)row * DD + col] = o;
                }
            }
        }
    } else if (tgout == nullptr) {
        // rrelu -> outp
        #pragma unroll
        for (int mt = 0; mt < 2; ++mt) {
            int r = row0 + wr * 32 + mt * 16 + (lane >> 2);
            #pragma unroll
            for (int nt = 0; nt < 13; ++nt) {
                int col = wc * 104 + nt * 8 + (lane & 3) * 2;
                if (col >= DD) continue;
                #pragma unroll
                for (int half = 0; half < 2; ++half) {
                    int row = r + half * 8;
                    if (row >= NN) continue;
                    float v0 = acc[mt][nt][half * 2];
                    float v1 = acc[mt][nt][half * 2 + 1];
                    float2 o;
                    o.x = (v0 >= 0.f) ? v0 : v0 * SLOPE;
                    o.y = (v1 >= 0.f) ? v1 : v1 * SLOPE;
                    *(float2*)&outp[(size_t)row * DD + col] = o;
                }
            }
        }
    } else {
        // fused layer-1 + time gate
        float sq[2][2] = {{0.f, 0.f}, {0.f, 0.f}};
        #pragma unroll
        for (int mt = 0; mt < 2; ++mt)
            #pragma unroll
            for (int nt = 0; nt < 13; ++nt) {
                int col = wc * 104 + nt * 8 + (lane & 3) * 2;
                #pragma unroll
                for (int half = 0; half < 2; ++half) {
                    float v0 = acc[mt][nt][half * 2];
                    float v1 = acc[mt][nt][half * 2 + 1];
                    v0 = (v0 >= 0.f) ? v0 : v0 * SLOPE;
                    v1 = (v1 >= 0.f) ? v1 : v1 * SLOPE;
                    acc[mt][nt][half * 2] = v0;
                    acc[mt][nt][half * 2 + 1] = v1;
                    if (col < DD) sq[mt][half] += v0 * v0 + v1 * v1;
                }
            }
        #pragma unroll
        for (int mt = 0; mt < 2; ++mt)
            #pragma unroll
            for (int half = 0; half < 2; ++half) {
                float v = sq[mt][half];
                v += __shfl_xor_sync(0xffffffffu, v, 1);
                v += __shfl_xor_sync(0xffffffffu, v, 2);
                if ((lane & 3) == 0)
                    atomicAdd(&s_ssq[wr * 32 + mt * 16 + (lane >> 2) + half * 8], v);
            }
        __syncthreads();
        #pragma unroll
        for (int mt = 0; mt < 2; ++mt) {
            int rl = wr * 32 + mt * 16 + (lane >> 2);
            #pragma unroll
            for (int nt = 0; nt < 13; ++nt) {
                int col = wc * 104 + nt * 8 + (lane & 3) * 2;
                if (col >= DD) continue;
                #pragma unroll
                for (int half = 0; half < 2; ++half) {
                    int row = row0 + rl + half * 8;
                    if (row >= NN) continue;
                    float sc = 1.f / fmaxf(sqrtf(s_ssq[rl + half * 8]), 1e-12f);
                    size_t off = (size_t)row * DD + col;
                    float2 ga = *(const float2*)&gaccp[off];
                    float2 ho = *(const float2*)&tghold[off];
                    float t0 = 1.f / (1.f + expf(-(ga.x + tgbt[col])));
                    float t1 = 1.f / (1.f + expf(-(ga.y + tgbt[col + 1])));
                    float2 hn;
                    hn.x = t0 * (acc[mt][nt][half * 2] * sc) + (1.f - t0) * ho.x;
                    hn.y = t1 * (acc[mt][nt][half * 2 + 1] * sc) + (1.f - t1) * ho.y;
                    *(float2*)&tgout[off] = hn;
                }
            }
        }
    }
    if (zaggp != nullptr) {
        float4 z = make_float4(0.f, 0.f, 0.f, 0.f);
        for (int i = tid; i < 128 * 50; i += 256) {
            int r = i / 50, q = i - r * 50;
            int row = row0 + r;
            if (row < NN) ((float4*)&zaggp[(size_t)row * DD])[q] = z;
        }
    }
}

// ---------------- GRU gates GEMM (tf32, BK=8) ----------------
__global__ void __launch_bounds__(256)
k_gates(const float* __restrict__ A0g, const float* __restrict__ B0g, int ldb0,
        const float* __restrict__ addc, float* __restrict__ out0,
        const float* __restrict__ A1g, const float* __restrict__ B1g, int ldb1,
        float* __restrict__ out1, int nparts) {
    __shared__ __align__(16) float sm[3 * 4032];
    int tid = threadIdx.x, lane = tid & 31, wid = tid >> 5;
    int wr = wid >> 1, wc = wid & 1;
    int row0 = blockIdx.x * 128;
    int cbase = blockIdx.y * 200;

    float acc[2][13][4];
    #pragma unroll
    for (int mt = 0; mt < 2; ++mt)
        #pragma unroll
        for (int nt = 0; nt < 13; ++nt)
            #pragma unroll
            for (int q = 0; q < 4; ++q) acc[mt][nt][q] = 0.f;

    const int nk = nparts * 25;

    auto issue = [&](int c) {
        if (c < nk) {
            const float* A = (c < 25) ? A0g : A1g;
            const float* B = (c < 25) ? B0g : B1g;
            int ldb = (c < 25) ? ldb0 : ldb1;
            int k0 = ((c < 25) ? c : c - 25) * 8;
            int base = (c % 3) * 4032;
            {
                int r = tid >> 1, h = tid & 1;
                int row = row0 + r;
                if (row >= RR) row = RR - 1;
                CP16(smem_u32(&sm[base + r * 12 + h * 4]),
                     A + (size_t)row * 200 + k0 + h * 4);
            }
            #pragma unroll
            for (int j = tid; j < 416; j += 256) {
                int n = j >> 1, h = j & 1;
                int nn = cbase + n;
                if (nn > 599) nn = 599;
                CP16(smem_u32(&sm[base + 1536 + n * 12 + h * 4]),
                     B + (size_t)nn * ldb + k0 + h * 4);
            }
        }
        CP_COMMIT();
    };

    auto writeout = [&](float* out, const float* adc) {
        #pragma unroll
        for (int mt = 0; mt < 2; ++mt) {
            int r = row0 + wr * 32 + mt * 16 + (lane >> 2);
            #pragma unroll
            for (int nt = 0; nt < 13; ++nt) {
                int col = wc * 104 + nt * 8 + (lane & 3) * 2;
                if (col >= 200) continue;
                #pragma unroll
                for (int half = 0; half < 2; ++half) {
                    int row = r + half * 8;
                    if (row >= RR) continue;
                    size_t off = (size_t)row * 600 + cbase + col;
                    float v0 = acc[mt][nt][half * 2];
                    float v1 = acc[mt][nt][half * 2 + 1];
                    if (adc) { v0 += adc[off]; v1 += adc[off + 1]; }
                    out[off] = v0;
                    out[off + 1] = v1;
                }
            }
        }
    };

    issue(0); issue(1); issue(2);
    for (int c = 0; c < nk; ++c) {
        CP_WAIT2();
        __syncthreads();
        int base = (c % 3) * 4032;
        uint32_t a[2][4];
        int rb = wr * 32 + (lane >> 2);
        int kk = lane & 3;
        #pragma unroll
        for (int mt = 0; mt < 2; ++mt) {
            int r = rb + mt * 16;
            a[mt][0] = __float_as_uint(sm[base + r * 12 + kk]);
            a[mt][1] = __float_as_uint(sm[base + (r + 8) * 12 + kk]);
            a[mt][2] = __float_as_uint(sm[base + r * 12 + kk + 4]);
            a[mt][3] = __float_as_uint(sm[base + (r + 8) * 12 + kk + 4]);
        }
        int nb = wc * 104 + (lane >> 2);
        #pragma unroll
        for (int nt = 0; nt < 13; ++nt) {
            int n = nb + nt * 8;
            uint32_t b0 = __float_as_uint(sm[base + 1536 + n * 12 + kk]);
            uint32_t b1 = __float_as_uint(sm[base + 1536 + n * 12 + kk + 4]);
            MMA_TF32(acc[0][nt], a[0], b0, b1);
            MMA_TF32(acc[1][nt], a[1], b0, b1);
        }
        if (c == 24 && nparts == 2) {
            writeout(out0, addc);
            #pragma unroll
            for (int mt = 0; mt < 2; ++mt)
                #pragma unroll
                for (int nt = 0; nt < 13; ++nt)
                    #pragma unroll
                    for (int q = 0; q < 4; ++q) acc[mt][nt][q] = 0.f;
        }
        __syncthreads();
        issue(c + 3);
    }
    if (nparts == 2) writeout(out1, nullptr);
    else writeout(out0, addc);
}

// ---------------- relation mean gather -> g_xmean ----------------
__global__ void __launch_bounds__(256)
k_relmean(const float* __restrict__ hh) {
    __shared__ __align__(16) float part[8 * DD];
    int r = blockIdx.x, tid = threadIdx.x, lane = tid & 31, wid = tid >> 5;
    int beg = g_roff[r], end = g_roff[r + 1];

    float4 a0 = make_float4(0.f, 0.f, 0.f, 0.f);
    float4 a1 = a0;
    for (int j = beg + wid; j < end; j += 8) {
        int ent = g_rlist[j];
        const float4* hs = (const float4*)(hh + (size_t)ent * DD);
        float4 x = hs[lane];
        a0.x += x.x; a0.y += x.y; a0.z += x.z; a0.w += x.w;
        if (lane < 18) {
            float4 u = hs[lane + 32];
            a1.x += u.x; a1.y += u.y; a1.z += u.z; a1.w += u.w;
        }
    }
    float4* pw = (float4*)(part + wid * DD);
    pw[lane] = a0;
    if (lane < 18) pw[lane + 32] = a1;
    __syncthreads();
    float inv_cnt = 1.f / fmaxf((float)(end - beg), 1.f);
    for (int d = tid; d < DD; d += 256) {
        float s = 0.f;
        #pragma unroll
        for (int w = 0; w < 8; ++w) s += part[w * DD + d];
        g_xmean[r * DD + d] = s * inv_cnt;
    }
}

// ---------------- GRU elementwise + l2norm ----------------
__global__ void __launch_bounds__(256)
k_gruelem(const float* __restrict__ hprev, const float* __restrict__ b_ih,
          const float* __restrict__ b_hh) {
    __shared__ float shn[DD];
    __shared__ float sred[8];
    int r = blockIdx.x, tid = threadIdx.x, lane = tid & 31, wid = tid >> 5;
    float ss = 0.f;
    for (int d = tid; d < DD; d += 256) {
        float gir = g_gi[r * 600 + d] + b_ih[d];
        float giz = g_gi[r * 600 + 200 + d] + b_ih[200 + d];
        float gin = g_gi[r * 600 + 400 + d] + b_ih[400 + d];
        float ghr = g_gh[r * 600 + d] + b_hh[d];
        float ghz = g_gh[r * 600 + 200 + d] + b_hh[200 + d];
        float ghn = g_gh[r * 600 + 400 + d] + b_hh[400 + d];
        float rg = 1.f / (1.f + expf(-(gir + ghr)));
        float zg = 1.f / (1.f + expf(-(giz + ghz)));
        float ng = tanhf(gin + rg * ghn);
        float hn = (1.f - zg) * ng + zg * hprev[r * DD + d];
        shn[d] = hn;
        ss += hn * hn;
    }
    #pragma unroll
    for (int o = 16; o; o >>= 1) ss += __shfl_xor_sync(0xffffffffu, ss, o);
    if (lane == 0) sred[wid] = ss;
    __syncthreads();
    if (tid == 0) {
        float t = 0.f;
        #pragma unroll
        for (int i = 0; i < 8; ++i) t += sred[i];
        sred[0] = t;
    }
    __syncthreads();
    float s = 1.f / fmaxf(sqrtf(sred[0]), 1e-12f);
    for (int d = tid; d < DD; d += 256) g_h0[r * DD + d] = shn[d] * s;
}

// ---------------- counts / scan / fill ----------------
__global__ void __launch_bounds__(256) k_count(const int* __restrict__ dst,
                                               const int* __restrict__ et) {
    __shared__ int hist[RR];
    for (int i = threadIdx.x; i < RR; i += 256) hist[i] = 0;
    __syncthreads();
    for (int e = blockIdx.x * blockDim.x + threadIdx.x; e < EE;
         e += gridDim.x * blockDim.x) {
        atomicAdd(&hist[et[e]], 2);
        atomicAdd(&g_iblk[2 * RR + dst[e]], 1);
    }
    __syncthreads();
    for (int i = threadIdx.x; i < RR; i += 256) {
        int c = hist[i];
        if (c) atomicAdd(&g_iblk[i], c);
    }
}

__global__ void __launch_bounds__(512) k_rscan() {
    __shared__ int s[512];
    int tid = threadIdx.x;
    int v = (tid < RR) ? g_iblk[tid] : 0;
    s[tid] = v;
    __syncthreads();
    for (int o = 1; o < 512; o <<= 1) {
        int u = (tid >= o) ? s[tid - o] : 0;
        __syncthreads();
        s[tid] += u;
        __syncthreads();
    }
    if (tid < RR) g_roff[tid] = s[tid] - v;
    if (tid == 0) g_roff[RR] = 2 * EE;
}

__global__ void __launch_bounds__(256)
k_rfill(const int* __restrict__ src, const int* __restrict__ dst,
        const int* __restrict__ et) {
    __shared__ int lh[RR];
    __shared__ int base[RR];
    for (int i = threadIdx.x; i < RR; i += 256) lh[i] = 0;
    __syncthreads();
    int e = blockIdx.x * blockDim.x + threadIdx.x;
    int s = 0, d_ = 0, r = 0, lr = 0;
    bool act = (e < EE);
    if (act) {
        s = src[e]; d_ = dst[e]; r = et[e];
        lr = atomicAdd(&lh[r], 2);
    }
    __syncthreads();
    for (int i = threadIdx.x; i < RR; i += 256) {
        int c = lh[i];
        base[i] = c ? atomicAdd(&g_iblk[RR + i], c) : 0;
    }
    __syncthreads();
    if (act) {
        int pos = g_roff[r] + base[r] + lr;
        g_rlist[pos] = s;
        g_rlist[pos + 1] = d_;
    }
}

// ---------------- edge scatter: agg[dst] += hh[src] + h0[et] ----------------
__global__ void k_edge(const int* __restrict__ src, const int* __restrict__ dst,
                       const int* __restrict__ et, const float* __restrict__ hh) {
    int idx = blockIdx.x * blockDim.x + threadIdx.x;
    if (idx >= EE * 25) return;
    int e = idx / 25, q = idx - e * 25;
    int s = src[e], dn = dst[e], r = et[e];
    const float4* hs = (const float4*)(hh + (size_t)s * DD) + 2 * q;
    const float4* h0 = (const float4*)(g_h0 + (size_t)r * DD) + 2 * q;
    float4 a = hs[0], b = h0[0];
    float4 c = hs[1], d2 = h0[1];
    float* p = g_agg + (size_t)dn * DD + q * 8;
    red_add_v4(p, make_float4(a.x + b.x, a.y + b.y, a.z + b.z, a.w + b.w));
    red_add_v4(p + 4, make_float4(c.x + d2.x, c.y + d2.y, c.z + d2.z, c.w + d2.w));
}

// ---------------- utility kernels ----------------
__global__ void k_transpose_all(const float* __restrict__ Wn, const float* __restrict__ Wl,
                                const float* __restrict__ Wt, float* __restrict__ Bt) {
    int idx = blockIdx.x * blockDim.x + threadIdx.x;
    if (idx >= 5 * DD * DD) return;
    int m = idx / (DD * DD);
    int r = idx - m * (DD * DD);
    int k = r / DD, n = r - k * DD;
    const float* W;
    if (m == 4) W = Wt;
    else if (m & 1) W = Wl + (m >> 1) * DD * DD;
    else W = Wn + (m >> 1) * DD * DD;
    Bt[m * DD * DD + n * DD + k] = W[r];
}
__global__ void k_l2norm_rows(const float* __restrict__ in, float* __restrict__ out, int nrows) {
    int w = (blockIdx.x * blockDim.x + threadIdx.x) >> 5;
    int lane = threadIdx.x & 31;
    if (w >= nrows) return;
    const float* r = in + (size_t)w * DD;
    float ss = 0.f;
    for (int d = lane; d < DD; d += 32) { float v = r[d]; ss += v * v; }
    #pragma unroll
    for (int o = 16; o; o >>= 1) ss += __shfl_xor_sync(0xffffffffu, ss, o);
    float s = 1.f / fmaxf(sqrtf(ss), 1e-12f);
    float* po = out + (size_t)w * DD;
    for (int d = lane; d < DD; d += 32) po[d] = r[d] * s;
}

// ---------------- host driver ----------------
extern "C" void kernel_launch(void* const* d_in, const int* in_sizes, int n_in,
                              void* d_out, int out_size) {
    const int* src = (const int*)d_in[0];
    const int* dst = (const int*)d_in[1];
    const int* et  = (const int*)d_in[2];
    const float* dyn     = (const float*)d_in[3];
    const float* emb_rel = (const float*)d_in[4];
    const float* W_ih    = (const float*)d_in[5];
    const float* W_hh    = (const float*)d_in[6];
    const float* b_ih    = (const float*)d_in[7];
    const float* b_hh    = (const float*)d_in[8];
    const float* W_nb    = (const float*)d_in[9];
    const float* W_lp    = (const float*)d_in[10];
    const float* Wt      = (const float*)d_in[11];
    const float* bt      = (const float*)d_in[12];
    float* out = (float*)d_out;

    float *p_h, *p_hhA, *p_agg, *p_gacc, *p_h0, *p_Bt;
    float *p_gic, *p_gi, *p_gh, *p_xmean;
    int* p_iblk;
    cudaGetSymbolAddress((void**)&p_h,     g_h);
    cudaGetSymbolAddress((void**)&p_hhA,   g_hhA);
    cudaGetSymbolAddress((void**)&p_agg,   g_agg);
    cudaGetSymbolAddress((void**)&p_gacc,  g_gacc);
    cudaGetSymbolAddress((void**)&p_h0,    g_h0);
    cudaGetSymbolAddress((void**)&p_Bt,    g_Bt);
    cudaGetSymbolAddress((void**)&p_gic,   g_gic);
    cudaGetSymbolAddress((void**)&p_gi,    g_gi);
    cudaGetSymbolAddress((void**)&p_gh,    g_gh);
    cudaGetSymbolAddress((void**)&p_xmean, g_xmean);
    cudaGetSymbolAddress((void**)&p_iblk,  g_iblk);
    int* p_deg = p_iblk + 2 * RR;

    const int gemm_blocks = (NN + 127) / 128;  // 391
    const int eb = (EE * 25 + 255) / 256;
    const int e1 = (EE + 255) / 256;
    const dim3 ggrid(4, 3);

    // prologue
    k_transpose_all<<<(5 * DD * DD + 255) / 256, 256>>>(W_nb, W_lp, Wt, p_Bt);
    k_l2norm_rows<<<(NN * 32 + 255) / 256, 256>>>(dyn, p_h, NN);
    k_gates<<<ggrid, 256>>>(emb_rel, W_ih, 400, nullptr, p_gic,
                            nullptr, nullptr, 0, nullptr, 1);
    cudaMemsetAsync(p_agg, 0, (size_t)NN * DD * sizeof(float));

    for (int t = 0; t < TT; ++t) {
        const int* s_t = src + t * EE;
        const int* d_t = dst + t * EE;
        const int* e_t = et  + t * EE;
        const float* hprev = (t == 0) ? emb_rel : p_h0;
        const float* hcur = (t == 0) ? p_h : out + (size_t)(t - 1) * NN * DD;
        float* hnext = out + (size_t)t * NN * DD;

        // CSR + GRU (batched gates GEMM)
        cudaMemsetAsync(p_iblk, 0, (2 * RR + NN) * sizeof(int));
        k_count<<<148, 256>>>(d_t, e_t);
        k_rscan<<<1, 512>>>();
        k_rfill<<<e1, 256>>>(s_t, d_t, e_t);
        k_relmean<<<RR, 256>>>(hcur);
        k_gates<<<ggrid, 256>>>(p_xmean, W_ih + 200, 400, p_gic, p_gi,
                                hprev, W_hh, 200, p_gh, 2);
        k_gruelem<<<RR, 256>>>(hprev, b_ih, b_hh);

        // layer 0 + time-gate GEMM merged (by=1: hcur @ Wt -> gacc)
        k_edge<<<eb, 256>>>(s_t, d_t, e_t, hcur);
        k_mma_gemm<<<dim3(gemm_blocks, 2), 256>>>(
            p_agg, hcur, p_Bt + 0 * DD * DD, p_Bt + 1 * DD * DD, p_deg,
            p_hhA, p_agg, p_Bt + 4 * DD * DD, p_gacc,
            nullptr, nullptr, nullptr, 2);

        // layer 1 + fused time gate: hnext written directly
        k_edge<<<eb, 256>>>(s_t, d_t, e_t, p_hhA);
        k_mma_gemm<<<dim3(gemm_blocks, 1), 256>>>(
            p_agg, p_hhA, p_Bt + 2 * DD * DD, p_Bt + 3 * DD * DD, p_deg,
            nullptr, p_agg, nullptr, p_gacc,
            bt, hcur, hnext, 2);
    }
}

// round 17
// speedup vs baseline: 1.1485x; 1.1485x over previous
#include <cuda_runtime.h>
#include <cstdint>
#include <math.h>

#define NN 50000
#define DD 200
#define RR 480
#define TT 4
#define EE 100000
#define SLOPE 0.22916666666666666f
#define IBN (2 * RR + NN)   // per-bank int scratch: rcnt | rwc | deg

// ---------------- device scratch (no allocations) ----------------
__device__ float g_h[NN * DD];
__device__ float g_hhA[NN * DD];
__device__ float g_hhB[NN * DD];
__device__ float g_agg[NN * DD];
__device__ float g_gacc[NN * DD];
__device__ float g_ssq[NN];
__device__ float g_h0[RR * DD];
__device__ float g_Bt[5 * DD * DD + 4096];
__device__ float g_gic[RR * 600];
__device__ float g_gi[RR * 600];
__device__ float g_gh[RR * 600];
__device__ float g_xmean[RR * DD];
__device__ int g_iblk[2][IBN];       // double-buffered CSR scratch
__device__ int g_roff[RR + 1];
__device__ int g_rlist[2 * EE];

// ---------------- helpers ----------------
__device__ __forceinline__ uint32_t smem_u32(const void* p) {
    uint32_t a;
    asm("{ .reg .u64 t; cvta.to.shared.u64 t, %1; cvt.u32.u64 %0, t; }" : "=r"(a) : "l"(p));
    return a;
}

#define CP16(sm_addr, gptr) \
    asm volatile("cp.async.ca.shared.global [%0], [%1], 16;" :: "r"(sm_addr), "l"(gptr))
#define CP16Z(sm_addr, gptr, sz) \
    asm volatile("cp.async.ca.shared.global [%0], [%1], 16, %2;" \
                 :: "r"(sm_addr), "l"(gptr), "r"(sz))
#define CP_COMMIT() asm volatile("cp.async.commit_group;" ::: "memory")
#define CP_WAIT2()  asm volatile("cp.async.wait_group 2;" ::: "memory")

#define MMA_TF32(d, a, b0, b1)                                                    \
    asm volatile("mma.sync.aligned.m16n8k8.row.col.f32.tf32.tf32.f32 "            \
                 "{%0,%1,%2,%3}, {%4,%5,%6,%7}, {%8,%9}, {%0,%1,%2,%3};"          \
                 : "+f"((d)[0]), "+f"((d)[1]), "+f"((d)[2]), "+f"((d)[3])         \
                 : "r"((a)[0]), "r"((a)[1]), "r"((a)[2]), "r"((a)[3]),            \
                   "r"(b0), "r"(b1))

__device__ __forceinline__ void red_add_v4(float* p, float4 v) {
    asm volatile("red.global.add.v4.f32 [%0], {%1, %2, %3, %4};"
                 :: "l"(p), "f"(v.x), "f"(v.y), "f"(v.z), "f"(v.w) : "memory");
}

// ---------------- fused tensor-core GEMM (tf32, BK=16, 3-stage pipe) ------------
// by==0: main GEMM: acc = sum_parts Apart @ Bpart^T; after part0 acc *= 1/deg;
//        out = rrelu(acc); optional ssq; optional zero zagg rows.
// by==1 && tgB!=null: time-gate GEMM: gacc = A1 @ tgB^T (raw).
// by==1 && tgB==null: COUNT service: histogram c_et / degree c_dst into c_iblk.
// by==2: ZERO service: zero zptr[0..IBN).
#define STG 6720
#define BOFF 2560

__global__ void __launch_bounds__(256, 2)
k_mma_gemm(const float* __restrict__ A0in, const float* __restrict__ A1,
           const float* __restrict__ B0in, const float* __restrict__ B1g,
           const int* __restrict__ degv, float* __restrict__ outp,
           float* __restrict__ ssqout, float* __restrict__ zaggp,
           const float* __restrict__ tgB, float* __restrict__ gaccp,
           const int* __restrict__ c_dst, const int* __restrict__ c_et,
           int* __restrict__ c_iblk, int* __restrict__ zptr, int nparts) {
    __shared__ __align__(16) float sm[3 * STG];
    __shared__ float s_ssq[128];
    int tid = threadIdx.x;

    if (blockIdx.y == 2) {  // zero service
        for (int i = blockIdx.x * 256 + tid; i < IBN; i += gridDim.x * 256)
            zptr[i] = 0;
        return;
    }
    if (blockIdx.y == 1 && tgB == nullptr) {  // count service
        int* hist = (int*)sm;
        for (int i = tid; i < RR; i += 256) hist[i] = 0;
        __syncthreads();
        for (int e = blockIdx.x * 256 + tid; e < EE; e += gridDim.x * 256) {
            atomicAdd(&hist[c_et[e]], 2);
            atomicAdd(&c_iblk[2 * RR + c_dst[e]], 1);
        }
        __syncthreads();
        for (int i = tid; i < RR; i += 256) {
            int c = hist[i];
            if (c) atomicAdd(&c_iblk[i], c);
        }
        return;
    }

    int lane = tid & 31, wid = tid >> 5;
    int wr = wid >> 1, wc = wid & 1;
    int row0 = blockIdx.x * 128;
    bool tg = (blockIdx.y == 1);
    const float* A0 = tg ? A1 : A0in;
    const float* B0g = tg ? tgB : B0in;
    int np = tg ? 1 : nparts;
    if (tg) { ssqout = nullptr; zaggp = nullptr; }
    if (tid < 128) s_ssq[tid] = 0.f;

    float acc[2][13][4];
    #pragma unroll
    for (int mt = 0; mt < 2; ++mt)
        #pragma unroll
        for (int nt = 0; nt < 13; ++nt)
            #pragma unroll
            for (int q = 0; q < 4; ++q) acc[mt][nt][q] = 0.f;

    const int nk = np * 13;

    auto issue = [&](int c) {
        if (c < nk) {
            const float* A = (c < 13) ? A0 : A1;
            const float* B = (c < 13) ? B0g : B1g;
            int k0 = ((c < 13) ? c : c - 13) * 16;
            int base = (c % 3) * STG;
            #pragma unroll
            for (int i = 0; i < 2; ++i) {
                int idx = tid + i * 256;
                int r = idx >> 2, c4 = idx & 3;
                int row = row0 + r;
                if (row >= NN) row = NN - 1;
                int kk = k0 + c4 * 4;
                uint32_t sz = (kk < DD) ? 16u : 0u;
                CP16Z(smem_u32(&sm[base + r * 20 + c4 * 4]),
                      A + (size_t)row * DD + (kk < DD ? kk : 0), sz);
            }
            #pragma unroll
            for (int i = 0; i < 4; ++i) {
                int idx = tid + i * 256;
                if (idx < 832) {
                    int n = idx >> 2, c4 = idx & 3;
                    int kk = k0 + c4 * 4;
                    uint32_t sz = (kk < DD) ? 16u : 0u;
                    CP16Z(smem_u32(&sm[base + BOFF + n * 20 + c4 * 4]),
                          B + (size_t)n * DD + (kk < DD ? kk : 0), sz);
                }
            }
        }
        CP_COMMIT();
    };

    issue(0); issue(1); issue(2);
    for (int c = 0; c < nk; ++c) {
        CP_WAIT2();
        __syncthreads();
        int base = (c % 3) * STG;
        int rb = wr * 32 + (lane >> 2);
        int kk = lane & 3;
        int nb = wc * 104 + (lane >> 2);
        #pragma unroll
        for (int ks = 0; ks < 2; ++ks) {
            int ko = ks * 8;
            uint32_t a[2][4];
            #pragma unroll
            for (int mt = 0; mt < 2; ++mt) {
                int r = rb + mt * 16;
                a[mt][0] = __float_as_uint(sm[base + r * 20 + ko + kk]);
                a[mt][1] = __float_as_uint(sm[base + (r + 8) * 20 + ko + kk]);
                a[mt][2] = __float_as_uint(sm[base + r * 20 + ko + kk + 4]);
                a[mt][3] = __float_as_uint(sm[base + (r + 8) * 20 + ko + kk + 4]);
            }
            #pragma unroll
            for (int nt = 0; nt < 13; ++nt) {
                int n = nb + nt * 8;
                uint32_t b0 = __float_as_uint(sm[base + BOFF + n * 20 + ko + kk]);
                uint32_t b1 = __float_as_uint(sm[base + BOFF + n * 20 + ko + kk + 4]);
                MMA_TF32(acc[0][nt], a[0], b0, b1);
                MMA_TF32(acc[1][nt], a[1], b0, b1);
            }
        }
        if (c == 12 && np == 2) {
            #pragma unroll
            for (int mt = 0; mt < 2; ++mt) {
                int r = row0 + wr * 32 + mt * 16 + (lane >> 2);
                int r2 = r + 8;
                float n0 = 1.f / fmaxf((float)degv[r < NN ? r : NN - 1], 1.f);
                float n1 = 1.f / fmaxf((float)degv[r2 < NN ? r2 : NN - 1], 1.f);
                #pragma unroll
                for (int nt = 0; nt < 13; ++nt) {
                    acc[mt][nt][0] *= n0; acc[mt][nt][1] *= n0;
                    acc[mt][nt][2] *= n1; acc[mt][nt][3] *= n1;
                }
            }
        }
        __syncthreads();
        issue(c + 3);
    }

    // ---- epilogue ----
    float sq[2][2] = {{0.f, 0.f}, {0.f, 0.f}};
    #pragma unroll
    for (int mt = 0; mt < 2; ++mt) {
        int r = row0 + wr * 32 + mt * 16 + (lane >> 2);
        #pragma unroll
        for (int nt = 0; nt < 13; ++nt) {
            int col = wc * 104 + nt * 8 + (lane & 3) * 2;
            if (col >= DD) continue;
            #pragma unroll
            for (int half = 0; half < 2; ++half) {
                int row = r + half * 8;
                if (row >= NN) continue;
                float v0 = acc[mt][nt][half * 2];
                float v1 = acc[mt][nt][half * 2 + 1];
                size_t off = (size_t)row * DD + col;
                float2 o;
                if (!tg) {
                    o.x = (v0 >= 0.f) ? v0 : v0 * SLOPE;
                    o.y = (v1 >= 0.f) ? v1 : v1 * SLOPE;
                    sq[mt][half] += o.x * o.x + o.y * o.y;
                    *(float2*)&outp[off] = o;
                } else {
                    o.x = v0; o.y = v1;
                    *(float2*)&gaccp[off] = o;
                }
            }
        }
    }
    if (ssqout != nullptr) {
        #pragma unroll
        for (int mt = 0; mt < 2; ++mt)
            #pragma unroll
            for (int half = 0; half < 2; ++half) {
                float v = sq[mt][half];
                v += __shfl_xor_sync(0xffffffffu, v, 1);
                v += __shfl_xor_sync(0xffffffffu, v, 2);
                if ((lane & 3) == 0)
                    atomicAdd(&s_ssq[wr * 32 + mt * 16 + (lane >> 2) + half * 8], v);
            }
        __syncthreads();
        if (tid < 128 && row0 + tid < NN) ssqout[row0 + tid] = s_ssq[tid];
    }
    if (zaggp != nullptr) {
        float4 z = make_float4(0.f, 0.f, 0.f, 0.f);
        for (int i = tid; i < 128 * 50; i += 256) {
            int r = i / 50, q = i - r * 50;
            int row = row0 + r;
            if (row < NN) ((float4*)&zaggp[(size_t)row * DD])[q] = z;
        }
    }
}

// ---------------- time-gate elementwise (+ packed rscan for next step) ----------
// blocks [0, nblk): hn = sigmoid(gacc+bt)*(hhB*rsqrt(ssq)) + (1-..)*hold -> outp
// last block (if scnt != null): exclusive scan of scnt[0..RR) -> g_roff
__global__ void __launch_bounds__(512)
k_tgelem(const float* __restrict__ bt, const float* __restrict__ hold,
         float* __restrict__ outp, const int* __restrict__ scnt) {
    __shared__ int s[512];
    int tid = threadIdx.x;
    if (scnt != nullptr && blockIdx.x == gridDim.x - 1) {
        int v = (tid < RR) ? scnt[tid] : 0;
        s[tid] = v;
        __syncthreads();
        for (int o = 1; o < 512; o <<= 1) {
            int u = (tid >= o) ? s[tid - o] : 0;
            __syncthreads();
            s[tid] += u;
            __syncthreads();
        }
        if (tid < RR) g_roff[tid] = s[tid] - v;
        if (tid == 0) g_roff[RR] = 2 * EE;
        return;
    }
    int idx = blockIdx.x * 512 + tid;
    if (idx >= NN * 50) return;
    int row = idx / 50, q = idx - row * 50;
    size_t off = (size_t)row * DD + q * 4;
    float sc = 1.f / fmaxf(sqrtf(g_ssq[row]), 1e-12f);
    float4 ga = *(const float4*)&g_gacc[off];
    float4 cu = *(const float4*)&g_hhB[off];
    float4 ho = *(const float4*)&hold[off];
    const float* btq = bt + q * 4;
    float4 hn;
    float t0 = 1.f / (1.f + expf(-(ga.x + btq[0])));
    float t1 = 1.f / (1.f + expf(-(ga.y + btq[1])));
    float t2 = 1.f / (1.f + expf(-(ga.z + btq[2])));
    float t3 = 1.f / (1.f + expf(-(ga.w + btq[3])));
    hn.x = t0 * (cu.x * sc) + (1.f - t0) * ho.x;
    hn.y = t1 * (cu.y * sc) + (1.f - t1) * ho.y;
    hn.z = t2 * (cu.z * sc) + (1.f - t2) * ho.z;
    hn.w = t3 * (cu.w * sc) + (1.f - t3) * ho.w;
    *(float4*)&outp[off] = hn;
}

// ---------------- GRU gates GEMM (tf32, BK=8) ----------------
__global__ void __launch_bounds__(256)
k_gates(const float* __restrict__ A0g, const float* __restrict__ B0g, int ldb0,
        const float* __restrict__ addc, float* __restrict__ out0,
        const float* __restrict__ A1g, const float* __restrict__ B1g, int ldb1,
        float* __restrict__ out1, int nparts) {
    __shared__ __align__(16) float sm[3 * 4032];
    int tid = threadIdx.x, lane = tid & 31, wid = tid >> 5;
    int wr = wid >> 1, wc = wid & 1;
    int row0 = blockIdx.x * 128;
    int cbase = blockIdx.y * 200;

    float acc[2][13][4];
    #pragma unroll
    for (int mt = 0; mt < 2; ++mt)
        #pragma unroll
        for (int nt = 0; nt < 13; ++nt)
            #pragma unroll
            for (int q = 0; q < 4; ++q) acc[mt][nt][q] = 0.f;

    const int nk = nparts * 25;

    auto issue = [&](int c) {
        if (c < nk) {
            const float* A = (c < 25) ? A0g : A1g;
            const float* B = (c < 25) ? B0g : B1g;
            int ldb = (c < 25) ? ldb0 : ldb1;
            int k0 = ((c < 25) ? c : c - 25) * 8;
            int base = (c % 3) * 4032;
            {
                int r = tid >> 1, h = tid & 1;
                int row = row0 + r;
                if (row >= RR) row = RR - 1;
                CP16(smem_u32(&sm[base + r * 12 + h * 4]),
                     A + (size_t)row * 200 + k0 + h * 4);
            }
            #pragma unroll
            for (int j = tid; j < 416; j += 256) {
                int n = j >> 1, h = j & 1;
                int nn = cbase + n;
                if (nn > 599) nn = 599;
                CP16(smem_u32(&sm[base + 1536 + n * 12 + h * 4]),
                     B + (size_t)nn * ldb + k0 + h * 4);
            }
        }
        CP_COMMIT();
    };

    auto writeout = [&](float* out, const float* adc) {
        #pragma unroll
        for (int mt = 0; mt < 2; ++mt) {
            int r = row0 + wr * 32 + mt * 16 + (lane >> 2);
            #pragma unroll
            for (int nt = 0; nt < 13; ++nt) {
                int col = wc * 104 + nt * 8 + (lane & 3) * 2;
                if (col >= 200) continue;
                #pragma unroll
                for (int half = 0; half < 2; ++half) {
                    int row = r + half * 8;
                    if (row >= RR) continue;
                    size_t off = (size_t)row * 600 + cbase + col;
                    float v0 = acc[mt][nt][half * 2];
                    float v1 = acc[mt][nt][half * 2 + 1];
                    if (adc) { v0 += adc[off]; v1 += adc[off + 1]; }
                    out[off] = v0;
                    out[off + 1] = v1;
                }
            }
        }
    };

    issue(0); issue(1); issue(2);
    for (int c = 0; c < nk; ++c) {
        CP_WAIT2();
        __syncthreads();
        int base = (c % 3) * 4032;
        uint32_t a[2][4];
        int rb = wr * 32 + (lane >> 2);
        int kk = lane & 3;
        #pragma unroll
        for (int mt = 0; mt < 2; ++mt) {
            int r = rb + mt * 16;
            a[mt][0] = __float_as_uint(sm[base + r * 12 + kk]);
            a[mt][1] = __float_as_uint(sm[base + (r + 8) * 12 + kk]);
            a[mt][2] = __float_as_uint(sm[base + r * 12 + kk + 4]);
            a[mt][3] = __float_as_uint(sm[base + (r + 8) * 12 + kk + 4]);
        }
        int nb = wc * 104 + (lane >> 2);
        #pragma unroll
        for (int nt = 0; nt < 13; ++nt) {
            int n = nb + nt * 8;
            uint32_t b0 = __float_as_uint(sm[base + 1536 + n * 12 + kk]);
            uint32_t b1 = __float_as_uint(sm[base + 1536 + n * 12 + kk + 4]);
            MMA_TF32(acc[0][nt], a[0], b0, b1);
            MMA_TF32(acc[1][nt], a[1], b0, b1);
        }
        if (c == 24 && nparts == 2) {
            writeout(out0, addc);
            #pragma unroll
            for (int mt = 0; mt < 2; ++mt)
                #pragma unroll
                for (int nt = 0; nt < 13; ++nt)
                    #pragma unroll
                    for (int q = 0; q < 4; ++q) acc[mt][nt][q] = 0.f;
        }
        __syncthreads();
        issue(c + 3);
    }
    if (nparts == 2) writeout(out1, nullptr);
    else writeout(out0, addc);
}

// ---------------- relation mean gather -> g_xmean ----------------
__global__ void __launch_bounds__(256)
k_relmean(const float* __restrict__ hh) {
    __shared__ __align__(16) float part[8 * DD];
    int r = blockIdx.x, tid = threadIdx.x, lane = tid & 31, wid = tid >> 5;
    int beg = g_roff[r], end = g_roff[r + 1];

    float4 a0 = make_float4(0.f, 0.f, 0.f, 0.f);
    float4 a1 = a0;
    for (int j = beg + wid; j < end; j += 8) {
        int ent = g_rlist[j];
        const float4* hs = (const float4*)(hh + (size_t)ent * DD);
        float4 x = hs[lane];
        a0.x += x.x; a0.y += x.y; a0.z += x.z; a0.w += x.w;
        if (lane < 18) {
            float4 u = hs[lane + 32];
            a1.x += u.x; a1.y += u.y; a1.z += u.z; a1.w += u.w;
        }
    }
    float4* pw = (float4*)(part + wid * DD);
    pw[lane] = a0;
    if (lane < 18) pw[lane + 32] = a1;
    __syncthreads();
    float inv_cnt = 1.f / fmaxf((float)(end - beg), 1.f);
    for (int d = tid; d < DD; d += 256) {
        float s = 0.f;
        #pragma unroll
        for (int w = 0; w < 8; ++w) s += part[w * DD + d];
        g_xmean[r * DD + d] = s * inv_cnt;
    }
}

// ---------------- GRU elementwise + l2norm ----------------
__global__ void __launch_bounds__(256)
k_gruelem(const float* __restrict__ hprev, const float* __restrict__ b_ih,
          const float* __restrict__ b_hh) {
    __shared__ float shn[DD];
    __shared__ float sred[8];
    int r = blockIdx.x, tid = threadIdx.x, lane = tid & 31, wid = tid >> 5;
    float ss = 0.f;
    for (int d = tid; d < DD; d += 256) {
        float gir = g_gi[r * 600 + d] + b_ih[d];
        float giz = g_gi[r * 600 + 200 + d] + b_ih[200 + d];
        float gin = g_gi[r * 600 + 400 + d] + b_ih[400 + d];
        float ghr = g_gh[r * 600 + d] + b_hh[d];
        float ghz = g_gh[r * 600 + 200 + d] + b_hh[200 + d];
        float ghn = g_gh[r * 600 + 400 + d] + b_hh[400 + d];
        float rg = 1.f / (1.f + expf(-(gir + ghr)));
        float zg = 1.f / (1.f + expf(-(giz + ghz)));
        float ng = tanhf(gin + rg * ghn);
        float hn = (1.f - zg) * ng + zg * hprev[r * DD + d];
        shn[d] = hn;
        ss += hn * hn;
    }
    #pragma unroll
    for (int o = 16; o; o >>= 1) ss += __shfl_xor_sync(0xffffffffu, ss, o);
    if (lane == 0) sred[wid] = ss;
    __syncthreads();
    if (tid == 0) {
        float t = 0.f;
        #pragma unroll
        for (int i = 0; i < 8; ++i) t += sred[i];
        sred[0] = t;
    }
    __syncthreads();
    float s = 1.f / fmaxf(sqrtf(sred[0]), 1e-12f);
    for (int d = tid; d < DD; d += 256) g_h0[r * DD + d] = shn[d] * s;
}

// ---------------- standalone CSR kernels (prologue only) ----------------
__global__ void __launch_bounds__(256) k_count(const int* __restrict__ dst,
                                               const int* __restrict__ et,
                                               int* __restrict__ bank) {
    __shared__ int hist[RR];
    for (int i = threadIdx.x; i < RR; i += 256) hist[i] = 0;
    __syncthreads();
    for (int e = blockIdx.x * blockDim.x + threadIdx.x; e < EE;
         e += gridDim.x * blockDim.x) {
        atomicAdd(&hist[et[e]], 2);
        atomicAdd(&bank[2 * RR + dst[e]], 1);
    }
    __syncthreads();
    for (int i = threadIdx.x; i < RR; i += 256) {
        int c = hist[i];
        if (c) atomicAdd(&bank[i], c);
    }
}

__global__ void __launch_bounds__(512) k_rscan(const int* __restrict__ bank) {
    __shared__ int s[512];
    int tid = threadIdx.x;
    int v = (tid < RR) ? bank[tid] : 0;
    s[tid] = v;
    __syncthreads();
    for (int o = 1; o < 512; o <<= 1) {
        int u = (tid >= o) ? s[tid - o] : 0;
        __syncthreads();
        s[tid] += u;
        __syncthreads();
    }
    if (tid < RR) g_roff[tid] = s[tid] - v;
    if (tid == 0) g_roff[RR] = 2 * EE;
}

__global__ void __launch_bounds__(256)
k_rfill(const int* __restrict__ src, const int* __restrict__ dst,
        const int* __restrict__ et, int* __restrict__ bank) {
    __shared__ int lh[RR];
    __shared__ int base[RR];
    for (int i = threadIdx.x; i < RR; i += 256) lh[i] = 0;
    __syncthreads();
    int e = blockIdx.x * blockDim.x + threadIdx.x;
    int s = 0, d_ = 0, r = 0, lr = 0;
    bool act = (e < EE);
    if (act) {
        s = src[e]; d_ = dst[e]; r = et[e];
        lr = atomicAdd(&lh[r], 2);
    }
    __syncthreads();
    for (int i = threadIdx.x; i < RR; i += 256) {
        int c = lh[i];
        base[i] = c ? atomicAdd(&bank[RR + i], c) : 0;
    }
    __syncthreads();
    if (act) {
        int pos = g_roff[r] + base[r] + lr;
        g_rlist[pos] = s;
        g_rlist[pos + 1] = d_;
    }
}

// ---------------- edge scatter: agg[dst] += hh[src] + h0[et] ----------------
__global__ void k_edge(const int* __restrict__ src, const int* __restrict__ dst,
                       const int* __restrict__ et, const float* __restrict__ hh) {
    int idx = blockIdx.x * blockDim.x + threadIdx.x;
    if (idx >= EE * 25) return;
    int e = idx / 25, q = idx - e * 25;
    int s = src[e], dn = dst[e], r = et[e];
    const float4* hs = (const float4*)(hh + (size_t)s * DD) + 2 * q;
    const float4* h0 = (const float4*)(g_h0 + (size_t)r * DD) + 2 * q;
    float4 a = hs[0], b = h0[0];
    float4 c = hs[1], d2 = h0[1];
    float* p = g_agg + (size_t)dn * DD + q * 8;
    red_add_v4(p, make_float4(a.x + b.x, a.y + b.y, a.z + b.z, a.w + b.w));
    red_add_v4(p + 4, make_float4(c.x + d2.x, c.y + d2.y, c.z + d2.z, c.w + d2.w));
}

// ---------------- utility kernels ----------------
__global__ void k_transpose_all(const float* __restrict__ Wn, const float* __restrict__ Wl,
                                const float* __restrict__ Wt, float* __restrict__ Bt) {
    int idx = blockIdx.x * blockDim.x + threadIdx.x;
    if (idx >= 5 * DD * DD) return;
    int m = idx / (DD * DD);
    int r = idx - m * (DD * DD);
    int k = r / DD, n = r - k * DD;
    const float* W;
    if (m == 4) W = Wt;
    else if (m & 1) W = Wl + (m >> 1) * DD * DD;
    else W = Wn + (m >> 1) * DD * DD;
    Bt[m * DD * DD + n * DD + k] = W[r];
}
__global__ void k_l2norm_rows(const float* __restrict__ in, float* __restrict__ out, int nrows) {
    int w = (blockIdx.x * blockDim.x + threadIdx.x) >> 5;
    int lane = threadIdx.x & 31;
    if (w >= nrows) return;
    const float* r = in + (size_t)w * DD;
    float ss = 0.f;
    for (int d = lane; d < DD; d += 32) { float v = r[d]; ss += v * v; }
    #pragma unroll
    for (int o = 16; o; o >>= 1) ss += __shfl_xor_sync(0xffffffffu, ss, o);
    float s = 1.f / fmaxf(sqrtf(ss), 1e-12f);
    float* po = out + (size_t)w * DD;
    for (int d = lane; d < DD; d += 32) po[d] = r[d] * s;
}

// ---------------- host driver ----------------
extern "C" void kernel_launch(void* const* d_in, const int* in_sizes, int n_in,
                              void* d_out, int out_size) {
    const int* src = (const int*)d_in[0];
    const int* dst = (const int*)d_in[1];
    const int* et  = (const int*)d_in[2];
    const float* dyn     = (const float*)d_in[3];
    const float* emb_rel = (const float*)d_in[4];
    const float* W_ih    = (const float*)d_in[5];
    const float* W_hh    = (const float*)d_in[6];
    const float* b_ih    = (const float*)d_in[7];
    const float* b_hh    = (const float*)d_in[8];
    const float* W_nb    = (const float*)d_in[9];
    const float* W_lp    = (const float*)d_in[10];
    const float* Wt      = (const float*)d_in[11];
    const float* bt      = (const float*)d_in[12];
    float* out = (float*)d_out;

    float *p_h, *p_hhA, *p_hhB, *p_agg, *p_gacc, *p_ssq, *p_h0, *p_Bt;
    float *p_gic, *p_gi, *p_gh, *p_xmean;
    int* p_iblk;
    cudaGetSymbolAddress((void**)&p_h,     g_h);
    cudaGetSymbolAddress((void**)&p_hhA,   g_hhA);
    cudaGetSymbolAddress((void**)&p_hhB,   g_hhB);
    cudaGetSymbolAddress((void**)&p_agg,   g_agg);
    cudaGetSymbolAddress((void**)&p_gacc,  g_gacc);
    cudaGetSymbolAddress((void**)&p_ssq,   g_ssq);
    cudaGetSymbolAddress((void**)&p_h0,    g_h0);
    cudaGetSymbolAddress((void**)&p_Bt,    g_Bt);
    cudaGetSymbolAddress((void**)&p_gic,   g_gic);
    cudaGetSymbolAddress((void**)&p_gi,    g_gi);
    cudaGetSymbolAddress((void**)&p_gh,    g_gh);
    cudaGetSymbolAddress((void**)&p_xmean, g_xmean);
    cudaGetSymbolAddress((void**)&p_iblk,  g_iblk);

    const int gemm_blocks = (NN + 127) / 128;  // 391
    const int eb = (EE * 25 + 255) / 256;
    const int e1 = (EE + 255) / 256;
    const int tgb = (NN * 50 + 511) / 512;     // 4883
    const dim3 ggrid(4, 3);

    // prologue: weights, init h, constant gate half, CSR(0) into bank 0
    k_transpose_all<<<(5 * DD * DD + 255) / 256, 256>>>(W_nb, W_lp, Wt, p_Bt);
    k_l2norm_rows<<<(NN * 32 + 255) / 256, 256>>>(dyn, p_h, NN);
    k_gates<<<ggrid, 256>>>(emb_rel, W_ih, 400, nullptr, p_gic,
                            nullptr, nullptr, 0, nullptr, 1);
    cudaMemsetAsync(p_agg, 0, (size_t)NN * DD * sizeof(float));
    cudaMemsetAsync(p_iblk, 0, IBN * sizeof(int));
    k_count<<<148, 256>>>(dst, et, p_iblk);
    k_rscan<<<1, 512>>>(p_iblk);
    k_rfill<<<e1, 256>>>(src, dst, et, p_iblk);

    for (int t = 0; t < TT; ++t) {
        const int* s_t = src + t * EE;
        const int* d_t = dst + t * EE;
        const int* e_t = et  + t * EE;
        const float* hprev = (t == 0) ? emb_rel : p_h0;
        const float* hcur = (t == 0) ? p_h : out + (size_t)(t - 1) * NN * DD;
        float* hnext = out + (size_t)t * NN * DD;
        int* bank  = p_iblk + (t & 1) * IBN;        // CSR of step t
        int* nbank = p_iblk + ((t + 1) & 1) * IBN;  // CSR of step t+1
        bool more = (t + 1 < TT);
        const int* s_n = src + (t + 1) * EE;
        const int* d_n = dst + (t + 1) * EE;
        const int* e_n = et  + (t + 1) * EE;

        // GRU chain (rlist/roff for step t already built)
        k_relmean<<<RR, 256>>>(hcur);
        k_gates<<<ggrid, 256>>>(p_xmean, W_ih + 200, 400, p_gic, p_gi,
                                hprev, W_hh, 200, p_gh, 2);
        k_gruelem<<<RR, 256>>>(hprev, b_ih, b_hh);

        // layer 0 + tg GEMM (y=1) + zero next bank (y=2, if more)
        k_edge<<<eb, 256>>>(s_t, d_t, e_t, hcur);
        k_mma_gemm<<<dim3(gemm_blocks, more ? 3 : 2), 256>>>(
            p_agg, hcur, p_Bt + 0 * DD * DD, p_Bt + 1 * DD * DD,
            bank + 2 * RR, p_hhA, nullptr, p_agg,
            p_Bt + 4 * DD * DD, p_gacc,
            nullptr, nullptr, nullptr, nbank, 2);

        // layer 1 (+ packed count for next step as y=1)
        k_edge<<<eb, 256>>>(s_t, d_t, e_t, p_hhA);
        k_mma_gemm<<<dim3(gemm_blocks, more ? 2 : 1), 256>>>(
            p_agg, p_hhA, p_Bt + 2 * DD * DD, p_Bt + 3 * DD * DD,
            bank + 2 * RR, p_hhB, p_ssq, p_agg,
            nullptr, nullptr,
            d_n, e_n, nbank, nullptr, 2);

        // time gate (+ packed rscan of next counts in last block)
        k_tgelem<<<tgb + (more ? 1 : 0), 512>>>(bt, hcur, hnext,
                                                more ? nbank : nullptr);

        // fill next step's relation lists
        if (more) k_rfill<<<e1, 256>>>(s_n, d_n, e_n, nbank);
    }
}